// round 5
// baseline (speedup 1.0000x reference)
#include <cuda_runtime.h>
#include <stdint.h>

// out[i, 0:8] = params[idx[i]] * xs[i, 0:8]
// xs: float32 [N, 8]; idx: int32 [N]; params: float32 [V]; out: float32 [N, 8]
// N = 4194304, V = 1048576.
//
// 2 threads per row (16B lane-contiguous streams, dense wavefronts), lane
// pairs broadcast the idx/param access. UNROLL=8 front-batched chains hide
// the idx(DRAM)->param(L2) dependent latency. Gather bypasses L1 (__ldcg);
// streams are evict-first so the 4 MB param table stays L2-resident.

#define N_ROWS  4194304
#define ITEMS   (2 * N_ROWS)                   // 8M float4 half-rows
#define UNROLL  8
#define THREADS 256
#define BLOCKS  (ITEMS / (UNROLL * THREADS))   // 4096

__global__ __launch_bounds__(THREADS, 4) void gather_mul_kernel(
    const float4* __restrict__ xs,     // [ITEMS]
    const int*    __restrict__ idx,    // [N] int32
    const float*  __restrict__ params, // [V]
    float4*       __restrict__ out)    // [ITEMS]
{
    const int t = blockIdx.x * THREADS + threadIdx.x;
    const int S = BLOCKS * THREADS;    // 1M items per sweep

    // 1) Batch the index loads (lane pairs share an address -> broadcast).
    int j[UNROLL];
#pragma unroll
    for (int k = 0; k < UNROLL; k++)
        j[k] = __ldcs(idx + ((t + k * S) >> 1));

    // 2) Batch the param gathers: L2-only (table is L2-resident, no L1 reuse).
    float p[UNROLL];
#pragma unroll
    for (int k = 0; k < UNROLL; k++)
        p[k] = __ldcg(params + j[k]);

    // 3) Batch the xs half-row loads: 16B lane-contiguous, evict-first.
    float4 x[UNROLL];
#pragma unroll
    for (int k = 0; k < UNROLL; k++)
        x[k] = __ldcs(xs + t + k * S);

    // 4) Multiply + streaming stores (evict-first).
#pragma unroll
    for (int k = 0; k < UNROLL; k++) {
        float4 o;
        o.x = p[k] * x[k].x;
        o.y = p[k] * x[k].y;
        o.z = p[k] * x[k].z;
        o.w = p[k] * x[k].w;
        __stcs(out + t + k * S, o);
    }
}

extern "C" void kernel_launch(void* const* d_in, const int* in_sizes, int n_in,
                              void* d_out, int out_size)
{
    const float4* xs     = (const float4*)d_in[0];
    const int*    idx    = (const int*)d_in[1];
    const float*  params = (const float*)d_in[2];
    float4*       out    = (float4*)d_out;

    gather_mul_kernel<<<BLOCKS, THREADS>>>(xs, idx, params, out);
}

// round 6
// speedup vs baseline: 1.0156x; 1.0156x over previous
#include <cuda_runtime.h>
#include <stdint.h>

// out[i, 0:8] = params[idx[i]] * xs[i, 0:8]
// xs: float32 [N, 8]; idx: int32 [N]; params: float32 [V]; out: float32 [N, 8]
// N = 4194304, V = 1048576.
//
// 2 threads per row (16B lane-contiguous, dense wavefronts). Warp-blocked
// CONTIGUOUS layout: each warp owns 32*UNROLL consecutive float4 items, so
// all of a warp's streaming traffic stays within one 2MB page / adjacent
// DRAM rows (better row-buffer + TLB locality than 16MB-apart grid sweeps).
// Gather is L2-only (__ldcg); streams are evict-first (__ldcs/__stcs) to keep
// the 4 MB param table L2-resident.

#define N_ROWS  4194304
#define ITEMS   (2 * N_ROWS)                   // 8M float4 half-rows
#define UNROLL  8
#define THREADS 256
#define WARPS   (THREADS / 32)
#define BLOCKS  (ITEMS / (THREADS * UNROLL))   // 4096

__global__ __launch_bounds__(THREADS, 4) void gather_mul_kernel(
    const float4* __restrict__ xs,     // [ITEMS]
    const int*    __restrict__ idx,    // [N] int32
    const float*  __restrict__ params, // [V]
    float4*       __restrict__ out)    // [ITEMS]
{
    const int lane = threadIdx.x & 31;
    const int warp = (blockIdx.x * WARPS) + (threadIdx.x >> 5);
    // Each warp owns items [warp*32*UNROLL, (warp+1)*32*UNROLL).
    const int base = warp * (32 * UNROLL) + lane;

    // 1) Batch the index loads (lane pairs share an address -> broadcast).
    int j[UNROLL];
#pragma unroll
    for (int k = 0; k < UNROLL; k++)
        j[k] = __ldcs(idx + ((base + 32 * k) >> 1));

    // 2) Batch the param gathers: L2-only (table is L2-resident, no L1 reuse).
    float p[UNROLL];
#pragma unroll
    for (int k = 0; k < UNROLL; k++)
        p[k] = __ldcg(params + j[k]);

    // 3) Batch the xs half-row loads: 16B lane-contiguous, evict-first.
    float4 x[UNROLL];
#pragma unroll
    for (int k = 0; k < UNROLL; k++)
        x[k] = __ldcs(xs + base + 32 * k);

    // 4) Multiply + streaming stores (evict-first).
#pragma unroll
    for (int k = 0; k < UNROLL; k++) {
        float4 o;
        o.x = p[k] * x[k].x;
        o.y = p[k] * x[k].y;
        o.z = p[k] * x[k].z;
        o.w = p[k] * x[k].w;
        __stcs(out + base + 32 * k, o);
    }
}

extern "C" void kernel_launch(void* const* d_in, const int* in_sizes, int n_in,
                              void* d_out, int out_size)
{
    const float4* xs     = (const float4*)d_in[0];
    const int*    idx    = (const int*)d_in[1];
    const float*  params = (const float*)d_in[2];
    float4*       out    = (float4*)d_out;

    gather_mul_kernel<<<BLOCKS, THREADS>>>(xs, idx, params, out);
}